// round 6
// baseline (speedup 1.0000x reference)
#include <cuda_runtime.h>

// STN bilinear sampler, v6 — warp-cooperative coordinate math.
// x: [32,256,256,32] f32 NHWC ; theta: [32,6] f32 ; out: same shape.
//
// Each warp covers a 4(ox) x 8(oy) pixel tile.
// Phase 1: lane l = p*8+r computes weights+indices for pixel (ox4*4+p, oy8*8+r)
//          -> 32 distinct pixels' coordinate math in ONE warp pass.
// Phase 2: iterate 8 rows; per row, 6 shuffles redistribute the row's Samp to
//          the 8 channel-group lanes of each pixel; gathers stay in the
//          wavefront-optimal layout (8 lanes/pixel, one float4 each).
// Depth-2 prefetch pipeline keeps 8 LDG.128 in flight per thread.

#define B_ 32
#define H_ 256
#define W_ 256
#define STEP (2.0f / 255.0f)
#define FULL 0xFFFFFFFFu

__global__ __launch_bounds__(256) void stn_kernel(
    const float4* __restrict__ xf,
    const float* __restrict__ theta,
    float4* __restrict__ out)
{
    int tid  = blockIdx.x * blockDim.x + threadIdx.x;
    int lane = tid & 31;
    int w    = tid >> 5;              // warp id: [0, 65536)
    int ox4  = w & 63;                // ox group (4 pixels wide)
    int oy8  = (w >> 6) & 31;         // oy group (8 rows tall)
    int b    = w >> 11;               // batch

    // ---- phase 1: per-lane distinct pixel coordinate math ----
    const float* t = theta + b * 6;
    float t0 = __ldg(t + 0), t1 = __ldg(t + 1), t2 = __ldg(t + 2);
    float t3 = __ldg(t + 3), t4 = __ldg(t + 4), t5 = __ldg(t + 5);

    int oxp = (ox4 << 2) + (lane >> 3);   // this lane's pixel (phase-1 role)
    int oyp = (oy8 << 3) + (lane & 7);

    float gx = -1.0f + (float)oxp * STEP;
    float gy = -1.0f + (float)oyp * STEP;

    // identical formula to reference: 0.5*(T·g + 1)*N, truncate toward zero
    float sx = 0.5f * (t0 * gx + t1 * gy + t2 + 1.0f) * (float)W_;
    float sy = 0.5f * (t3 * gx + t4 * gy + t5 + 1.0f) * (float)H_;

    int x0 = (int)sx;
    int y0 = (int)sy;
    int x0c = min(max(x0, 0), W_ - 1);
    int x1c = min(max(x0 + 1, 0), W_ - 1);
    int y0c = min(max(y0, 0), H_ - 1);
    int y1c = min(max(y0 + 1, 0), H_ - 1);

    float x0f = (float)x0c, x1f = (float)x1c;
    float y0f = (float)y0c, y1f = (float)y1c;

    float mwa = (x1f - sx) * (y1f - sy);
    float mwb = (x1f - sx) * (sy - y0f);
    float mwc = (sx - x0f) * (y1f - sy);
    float mwd = (sx - x0f) * (sy - y0f);

    int basep = b << 16;
    // ia0: float4-unit base index of neighbor A (bits 0..23), dx flag in bit 24
    int ia0 = ((basep + (y0c << 8) + x0c) << 3) | ((x1c - x0c) << 24);
    int ib0 = ((basep + (y1c << 8) + x0c) << 3);

    // ---- phase 2: consume rows; lane role = (pixel p = lane>>3, cg = lane&7)
    int cg      = lane & 7;
    int srcbase = lane & 24;          // source lane group for my pixel
    int obase   = ((basep + (oy8 << 11) + (ox4 << 2) + (lane >> 3)) << 3) + cg;

    float wa[2], wb[2], wc[2], wd[2];
    float4 pa[2], pb[2], pc[2], pd[2];

    // prologue: fetch row 0
    {
        int src = srcbase;
        wa[0] = __shfl_sync(FULL, mwa, src);
        wb[0] = __shfl_sync(FULL, mwb, src);
        wc[0] = __shfl_sync(FULL, mwc, src);
        wd[0] = __shfl_sync(FULL, mwd, src);
        int iap = __shfl_sync(FULL, ia0, src);
        int ibv = __shfl_sync(FULL, ib0, src) + cg;
        int iav = (iap & 0x00FFFFFF) + cg;
        int dx8 = (iap >> 21) & 8;
        pa[0] = __ldg(xf + iav);
        pc[0] = __ldg(xf + iav + dx8);
        pb[0] = __ldg(xf + ibv);
        pd[0] = __ldg(xf + ibv + dx8);
    }

#pragma unroll
    for (int k = 0; k < 8; k++) {
        int cur = k & 1, nxt = cur ^ 1;

        if (k < 7) {   // prefetch row k+1 (shuffles + gathers)
            int src = srcbase + k + 1;
            wa[nxt] = __shfl_sync(FULL, mwa, src);
            wb[nxt] = __shfl_sync(FULL, mwb, src);
            wc[nxt] = __shfl_sync(FULL, mwc, src);
            wd[nxt] = __shfl_sync(FULL, mwd, src);
            int iap = __shfl_sync(FULL, ia0, src);
            int ibv = __shfl_sync(FULL, ib0, src) + cg;
            int iav = (iap & 0x00FFFFFF) + cg;
            int dx8 = (iap >> 21) & 8;
            pa[nxt] = __ldg(xf + iav);
            pc[nxt] = __ldg(xf + iav + dx8);
            pb[nxt] = __ldg(xf + ibv);
            pd[nxt] = __ldg(xf + ibv + dx8);
        }

        float4 o;
        o.x = wa[cur] * pa[cur].x + wb[cur] * pb[cur].x
            + wc[cur] * pc[cur].x + wd[cur] * pd[cur].x;
        o.y = wa[cur] * pa[cur].y + wb[cur] * pb[cur].y
            + wc[cur] * pc[cur].y + wd[cur] * pd[cur].y;
        o.z = wa[cur] * pa[cur].z + wb[cur] * pb[cur].z
            + wc[cur] * pc[cur].z + wd[cur] * pd[cur].z;
        o.w = wa[cur] * pa[cur].w + wb[cur] * pb[cur].w
            + wc[cur] * pc[cur].w + wd[cur] * pd[cur].w;

        // streaming store: output is write-once, keep L2 for the gather set
        __stcs(out + obase + (k << 11), o);   // + k * W_ * 8
    }
}

extern "C" void kernel_launch(void* const* d_in, const int* in_sizes, int n_in,
                              void* d_out, int out_size)
{
    const float4* x    = (const float4*)d_in[0];
    const float* theta = (const float*)d_in[1];
    float4* out = (float4*)d_out;

    // 65536 warps (32 pixels each) = 2,097,152 threads
    int block = 256;
    int grid  = (B_ * (H_ / 8) * (W_ / 4) * 32) / block;   // 8192
    stn_kernel<<<grid, block>>>(x, theta, out);
}

// round 7
// speedup vs baseline: 1.0160x; 1.0160x over previous
#include <cuda_runtime.h>

// STN bilinear sampler, v7 — explicit 2-row load batching (8 LDG.128 in flight).
// x: [32,256,256,32] f32 NHWC ; theta: [32,6] f32 ; out: same shape.
// Layout (wavefront-optimal, from v3): 8 threads/pixel, one float4 each ->
// each gather LDG.128 touches exactly 4 distinct 128B input lines per warp.
// One thread covers 8 output rows as 4 groups of 2; within a group all 8
// gather loads are issued before any FMA consumes them.

#define B_ 32
#define H_ 256
#define W_ 256
#define STEP (2.0f / 255.0f)

struct Samp {
    float wa, wb, wc, wd;
    int ia, ib, dx;
};

__device__ __forceinline__ Samp make_samp(
    float gx, float gy,
    float t0, float t1, float t2, float t3, float t4, float t5,
    int basep, int cg)
{
    // identical formula to reference: 0.5*(T·g + 1)*N, truncate toward zero
    float sx = 0.5f * (t0 * gx + t1 * gy + t2 + 1.0f) * (float)W_;
    float sy = 0.5f * (t3 * gx + t4 * gy + t5 + 1.0f) * (float)H_;

    int x0 = (int)sx;
    int y0 = (int)sy;

    int x0c = min(max(x0, 0), W_ - 1);
    int x1c = min(max(x0 + 1, 0), W_ - 1);
    int y0c = min(max(y0, 0), H_ - 1);
    int y1c = min(max(y0 + 1, 0), H_ - 1);

    float x0f = (float)x0c, x1f = (float)x1c;
    float y0f = (float)y0c, y1f = (float)y1c;

    Samp s;
    s.wa = (x1f - sx) * (y1f - sy);
    s.wb = (x1f - sx) * (sy - y0f);
    s.wc = (sx - x0f) * (y1f - sy);
    s.wd = (sx - x0f) * (sy - y0f);
    s.dx = (x1c - x0c) << 3;
    s.ia = ((basep + (y0c << 8) + x0c) << 3) + cg;
    s.ib = ((basep + (y1c << 8) + x0c) << 3) + cg;
    return s;
}

__global__ __launch_bounds__(256, 4) void stn_kernel(
    const float4* __restrict__ xf,
    const float* __restrict__ theta,
    float4* __restrict__ out)
{
    int gid = blockIdx.x * blockDim.x + threadIdx.x;   // [0, 2^21)
    int cg  = gid & 7;                 // channel group (float4 within pixel)
    int ox  = (gid >> 3) & 255;
    int oy8 = (gid >> 11) & 31;        // 8-row group index
    int b   = gid >> 16;               // batch
    int oy  = oy8 << 3;

    // affine params (uniform per batch, L1 broadcast) — amortized over 8 rows
    const float* t = theta + b * 6;
    float t0 = __ldg(t + 0), t1 = __ldg(t + 1), t2 = __ldg(t + 2);
    float t3 = __ldg(t + 3), t4 = __ldg(t + 4), t5 = __ldg(t + 5);

    float gx = -1.0f + (float)ox * STEP;
    int basep = b << 16;               // b * H*W
    int obase = ((basep + (oy << 8) + ox) << 3) + cg;

#pragma unroll
    for (int g = 0; g < 4; g++) {
        int r0 = oy + (g << 1);

        float gy0 = -1.0f + (float)r0 * STEP;
        float gy1 = -1.0f + (float)(r0 + 1) * STEP;

        Samp s0 = make_samp(gx, gy0, t0, t1, t2, t3, t4, t5, basep, cg);
        Samp s1 = make_samp(gx, gy1, t0, t1, t2, t3, t4, t5, basep, cg);

        // 8 independent LDG.128 issued before any consumption
        float4 pa0 = __ldg(xf + s0.ia);
        float4 pc0 = __ldg(xf + s0.ia + s0.dx);
        float4 pb0 = __ldg(xf + s0.ib);
        float4 pd0 = __ldg(xf + s0.ib + s0.dx);
        float4 pa1 = __ldg(xf + s1.ia);
        float4 pc1 = __ldg(xf + s1.ia + s1.dx);
        float4 pb1 = __ldg(xf + s1.ib);
        float4 pd1 = __ldg(xf + s1.ib + s1.dx);

        float4 o0, o1;
        o0.x = s0.wa * pa0.x + s0.wb * pb0.x + s0.wc * pc0.x + s0.wd * pd0.x;
        o0.y = s0.wa * pa0.y + s0.wb * pb0.y + s0.wc * pc0.y + s0.wd * pd0.y;
        o0.z = s0.wa * pa0.z + s0.wb * pb0.z + s0.wc * pc0.z + s0.wd * pd0.z;
        o0.w = s0.wa * pa0.w + s0.wb * pb0.w + s0.wc * pc0.w + s0.wd * pd0.w;

        o1.x = s1.wa * pa1.x + s1.wb * pb1.x + s1.wc * pc1.x + s1.wd * pd1.x;
        o1.y = s1.wa * pa1.y + s1.wb * pb1.y + s1.wc * pc1.y + s1.wd * pd1.y;
        o1.z = s1.wa * pa1.z + s1.wb * pb1.z + s1.wc * pc1.z + s1.wd * pd1.z;
        o1.w = s1.wa * pa1.w + s1.wb * pb1.w + s1.wc * pc1.w + s1.wd * pd1.w;

        // streaming stores: output is write-once, keep L2 for the gather set
        int oo = obase + (g << 12);            // (2g rows) * W_ * 8
        __stcs(out + oo, o0);
        __stcs(out + oo + (1 << 11), o1);
    }
}

extern "C" void kernel_launch(void* const* d_in, const int* in_sizes, int n_in,
                              void* d_out, int out_size)
{
    const float4* x    = (const float4*)d_in[0];
    const float* theta = (const float*)d_in[1];
    float4* out = (float4*)d_out;

    int total_threads = B_ * (H_ / 8) * W_ * 8;   // 2,097,152
    int block = 256;
    int grid = total_threads / block;              // 8,192
    stn_kernel<<<grid, block>>>(x, theta, out);
}